// round 2
// baseline (speedup 1.0000x reference)
#include <cuda_runtime.h>
#include <math.h>

#define BB    8
#define CIN   256
#define RELC  32
#define OUTC  256
#define SHAREC 8
#define GG    32       // groups
#define MID   320      // 32 + 32*9
#define MIDP  384      // padded to 3x128 for GEMM tiling
#define WOUT  288      // 9*32
#define HH    64
#define WWID  64
#define P     4096     // HH*WWID

// ---------------- scratch (static device arrays; no allocation) ----------------
__device__ float g_y[(size_t)BB * MID * P];     // conv1x1 outputs: [b][c][p]
__device__ float g_t[(size_t)BB * GG * P];      // weight-gen hidden: [b][g][p]
__device__ float g_w[(size_t)BB * WOUT * P];    // per-pixel kernels: [b][g*9+k][p]
__device__ float g_Wc[MIDP * CIN];              // packed conv weights (zero-padded rows 320..383)
__device__ float g_bias[MIDP];
__device__ float g_bn1s[MID];
__device__ float g_bn1b[MID];
__device__ float g_bn2s[GG];
__device__ float g_bn2b[GG];

// ---------------- f32x2 helpers ----------------
__device__ __forceinline__ unsigned long long pack2(float a, float b) {
    unsigned long long r;
    asm("mov.b64 %0, {%1, %2};" : "=l"(r) : "f"(a), "f"(b));
    return r;
}
__device__ __forceinline__ void fma2(unsigned long long& d, unsigned long long a, unsigned long long b) {
    asm("fma.rn.f32x2 %0, %1, %2, %0;" : "+l"(d) : "l"(a), "l"(b));
}
__device__ __forceinline__ void unpack2(unsigned long long v, float& lo, float& hi) {
    asm("mov.b64 {%0, %1}, %2;" : "=f"(lo), "=f"(hi) : "l"(v));
}

// ---------------- K0: pack weights + fold BN params ----------------
__global__ void pack_kernel(const float* __restrict__ w1, const float* __restrict__ b1,
                            const float* __restrict__ w2, const float* __restrict__ b2,
                            const float* __restrict__ w3, const float* __restrict__ b3,
                            const float* __restrict__ bn1_g, const float* __restrict__ bn1_b,
                            const float* __restrict__ bn1_m, const float* __restrict__ bn1_v,
                            const float* __restrict__ bn2_g, const float* __restrict__ bn2_b,
                            const float* __restrict__ bn2_m, const float* __restrict__ bn2_v) {
    int c = blockIdx.x * blockDim.x + threadIdx.x;
    if (c >= MIDP) return;
    if (c >= MID) {   // zero padding rows
        for (int k = 0; k < CIN; k++) g_Wc[c * CIN + k] = 0.f;
        g_bias[c] = 0.f;
        return;
    }
    const float* src;
    float bv;
    if (c < 32)      { src = w1 + (size_t)c * CIN;        bv = b1[c]; }
    else if (c < 64) { src = w2 + (size_t)(c - 32) * CIN; bv = b2[c - 32]; }
    else             { src = w3 + (size_t)(c - 64) * CIN; bv = b3[c - 64]; }
    for (int k = 0; k < CIN; k++) g_Wc[c * CIN + k] = src[k];
    g_bias[c] = bv;
    float s = bn1_g[c] * rsqrtf(bn1_v[c] + 1e-5f);
    g_bn1s[c] = s;
    g_bn1b[c] = bn1_b[c] - bn1_m[c] * s;
    if (c < GG) {
        float s2 = bn2_g[c] * rsqrtf(bn2_v[c] + 1e-5f);
        g_bn2s[c] = s2;
        g_bn2b[c] = bn2_b[c] - bn2_m[c] * s2;
    }
}

// ---------------- K1: fused conv1x1 GEMM  y[b,m,p] = Wc[m,:] . x[b,:,p] + bias[m] ----------------
// BM=128, BN=128, BK=16; 256 threads; 8x8 microtile, f32x2 FMA.
__global__ __launch_bounds__(256, 2) void conv1x1_kernel(const float* __restrict__ x) {
    const int b  = blockIdx.z;
    const int m0 = blockIdx.y * 128;
    const int n0 = blockIdx.x * 128;
    __shared__ float As[16][128];   // As[k][m]
    __shared__ float Bs[16][128];   // Bs[k][n]

    const int tid = threadIdx.x;
    const int tx = tid & 15;       // n-group (8 n each)
    const int ty = tid >> 4;       // m-group (8 m each)
    const float* xb = x + (size_t)b * CIN * P;

    unsigned long long acc[8][4];
#pragma unroll
    for (int i = 0; i < 8; i++)
#pragma unroll
        for (int j = 0; j < 4; j++) acc[i][j] = 0ull;

    const int mA  = tid >> 1;
    const int k8A = (tid & 1) * 8;
    const int kB  = tid >> 4;
    const int n8B = (tid & 15) * 8;

    for (int kk = 0; kk < CIN; kk += 16) {
        // A tile: 128 m x 16 k (transposed into As[k][m])
        float4 v0 = *(const float4*)&g_Wc[(size_t)(m0 + mA) * CIN + kk + k8A];
        float4 v1 = *(const float4*)&g_Wc[(size_t)(m0 + mA) * CIN + kk + k8A + 4];
        As[k8A + 0][mA] = v0.x; As[k8A + 1][mA] = v0.y;
        As[k8A + 2][mA] = v0.z; As[k8A + 3][mA] = v0.w;
        As[k8A + 4][mA] = v1.x; As[k8A + 5][mA] = v1.y;
        As[k8A + 6][mA] = v1.z; As[k8A + 7][mA] = v1.w;
        // B tile: 16 k x 128 n (contiguous n)
        *(float4*)&Bs[kB][n8B]     = *(const float4*)&xb[(size_t)(kk + kB) * P + n0 + n8B];
        *(float4*)&Bs[kB][n8B + 4] = *(const float4*)&xb[(size_t)(kk + kB) * P + n0 + n8B + 4];
        __syncthreads();
#pragma unroll
        for (int k = 0; k < 16; k++) {
            float4 a0 = *(const float4*)&As[k][ty * 8];
            float4 a1 = *(const float4*)&As[k][ty * 8 + 4];
            ulonglong2 bq0 = *(const ulonglong2*)&Bs[k][tx * 8];
            ulonglong2 bq1 = *(const ulonglong2*)&Bs[k][tx * 8 + 4];
            unsigned long long bp0 = bq0.x, bp1 = bq0.y, bp2 = bq1.x, bp3 = bq1.y;
            float av[8] = {a0.x, a0.y, a0.z, a0.w, a1.x, a1.y, a1.z, a1.w};
#pragma unroll
            for (int i = 0; i < 8; i++) {
                unsigned long long pa = pack2(av[i], av[i]);
                fma2(acc[i][0], pa, bp0);
                fma2(acc[i][1], pa, bp1);
                fma2(acc[i][2], pa, bp2);
                fma2(acc[i][3], pa, bp3);
            }
        }
        __syncthreads();
    }
#pragma unroll
    for (int i = 0; i < 8; i++) {
        int m = m0 + ty * 8 + i;
        if (m >= MID) break;
        float bv = g_bias[m];
        float o[8];
#pragma unroll
        for (int j = 0; j < 4; j++) {
            unpack2(acc[i][j], o[2 * j], o[2 * j + 1]);
            o[2 * j] += bv; o[2 * j + 1] += bv;
        }
        float* yr = g_y + ((size_t)b * MID + m) * P + n0 + tx * 8;
        *(float4*)&yr[0] = make_float4(o[0], o[1], o[2], o[3]);
        *(float4*)&yr[4] = make_float4(o[4], o[5], o[6], o[7]);
    }
}

// ---------------- h(c,p): BN1+ReLU of [x1 ; unfold_reflect(x2)] computed on the fly ----------------
__device__ __forceinline__ float h_val(const float* __restrict__ yb, int c, int p) {
    float v;
    if (c < 32) {
        v = yb[(size_t)c * P + p];
    } else {
        int cc = c - 32;
        int r = cc / 9, k = cc - r * 9;
        int ki = k / 3 - 1, kj = k - (k / 3) * 3 - 1;
        int i = (p >> 6) + ki;
        int j = (p & 63) + kj;
        i = (i < 0) ? 1 : (i > 63 ? 62 : i);   // reflect pad (pad=1)
        j = (j < 0) ? 1 : (j > 63 ? 62 : j);
        v = yb[(size_t)(32 + r) * P + (i << 6) + j];
    }
    v = v * g_bn1s[c] + g_bn1b[c];
    return fmaxf(v, 0.f);
}

// ---------------- K3: t[b,g,p] = relu(bn2( cw1[g,:] . h[b,:,p] )) ----------------
// BM=32 (all groups), BN=256 pixels, BK=16; 256 threads; 4g x 8p microtile, f32x2.
__global__ __launch_bounds__(256) void wgen1_kernel(const float* __restrict__ cw1) {
    const int b  = blockIdx.y;
    const int p0 = blockIdx.x * 256;
    __shared__ float As[16][32];    // As[k][g]
    __shared__ float Hs[16][256];   // Hs[k][n]
    const float* yb = g_y + (size_t)b * MID * P;
    const int tid = threadIdx.x;
    const int px = tid & 31;   // 32 column-groups of 8
    const int gq = tid >> 5;   // 8 row-groups of 4

    unsigned long long acc[4][4];
#pragma unroll
    for (int i = 0; i < 4; i++)
#pragma unroll
        for (int j = 0; j < 4; j++) acc[i][j] = 0ull;

    for (int kk = 0; kk < MID; kk += 16) {
#pragma unroll
        for (int e = 0; e < 2; e++) {
            int idx = tid + e * 256;
            int k = idx >> 5, g = idx & 31;
            As[k][g] = cw1[g * MID + kk + k];
        }
#pragma unroll
        for (int e = 0; e < 16; e++) {
            Hs[e][tid] = h_val(yb, kk + e, p0 + tid);
        }
        __syncthreads();
#pragma unroll
        for (int k = 0; k < 16; k++) {
            float4 a = *(const float4*)&As[k][gq * 4];
            ulonglong2 bq0 = *(const ulonglong2*)&Hs[k][px * 8];
            ulonglong2 bq1 = *(const ulonglong2*)&Hs[k][px * 8 + 4];
            unsigned long long bp0 = bq0.x, bp1 = bq0.y, bp2 = bq1.x, bp3 = bq1.y;
            float av[4] = {a.x, a.y, a.z, a.w};
#pragma unroll
            for (int i = 0; i < 4; i++) {
                unsigned long long pa = pack2(av[i], av[i]);
                fma2(acc[i][0], pa, bp0);
                fma2(acc[i][1], pa, bp1);
                fma2(acc[i][2], pa, bp2);
                fma2(acc[i][3], pa, bp3);
            }
        }
        __syncthreads();
    }
#pragma unroll
    for (int i = 0; i < 4; i++) {
        int g = gq * 4 + i;
        float s = g_bn2s[g], sh = g_bn2b[g];
        float o[8];
#pragma unroll
        for (int j = 0; j < 4; j++) {
            float lo, hi;
            unpack2(acc[i][j], lo, hi);
            o[2 * j]     = fmaxf(lo * s + sh, 0.f);
            o[2 * j + 1] = fmaxf(hi * s + sh, 0.f);
        }
        float* tr = g_t + ((size_t)b * GG + g) * P + p0 + px * 8;
        *(float4*)&tr[0] = make_float4(o[0], o[1], o[2], o[3]);
        *(float4*)&tr[4] = make_float4(o[4], o[5], o[6], o[7]);
    }
}

// ---------------- K4: w[b,o,p] = cw2[o,:] . t[b,:,p] + cb2[o] ----------------
// Block: 32 outputs x 256 pixels; K=32 fully unrolled; 4o x 8p microtile, f32x2.
__global__ __launch_bounds__(256) void wgen2_kernel(const float* __restrict__ cw2,
                                                    const float* __restrict__ cb2) {
    const int b  = blockIdx.z;
    const int o0 = blockIdx.y * 32;
    const int p0 = blockIdx.x * 256;
    __shared__ float ts[GG][256];     // 32KB
    __shared__ float w2t[GG][32];     // transposed weights: w2t[k][o]
    const int tid = threadIdx.x;

#pragma unroll
    for (int e = 0; e < GG; e++) {
        ts[e][tid] = g_t[((size_t)b * GG + e) * P + p0 + tid];
    }
    {
        int o  = tid >> 3;
        int k4 = (tid & 7) * 4;
        float4 w = *(const float4*)&cw2[(size_t)(o0 + o) * GG + k4];
        w2t[k4 + 0][o] = w.x; w2t[k4 + 1][o] = w.y;
        w2t[k4 + 2][o] = w.z; w2t[k4 + 3][o] = w.w;
    }
    __syncthreads();

    const int px = tid & 31;   // 8 pixels each
    const int oq = tid >> 5;   // 4 outputs each

    unsigned long long acc[4][4];
#pragma unroll
    for (int i = 0; i < 4; i++)
#pragma unroll
        for (int j = 0; j < 4; j++) acc[i][j] = 0ull;

#pragma unroll
    for (int k = 0; k < GG; k++) {
        float4 a = *(const float4*)&w2t[k][oq * 4];
        ulonglong2 bq0 = *(const ulonglong2*)&ts[k][px * 8];
        ulonglong2 bq1 = *(const ulonglong2*)&ts[k][px * 8 + 4];
        unsigned long long bp0 = bq0.x, bp1 = bq0.y, bp2 = bq1.x, bp3 = bq1.y;
        float av[4] = {a.x, a.y, a.z, a.w};
#pragma unroll
        for (int i = 0; i < 4; i++) {
            unsigned long long pa = pack2(av[i], av[i]);
            fma2(acc[i][0], pa, bp0);
            fma2(acc[i][1], pa, bp1);
            fma2(acc[i][2], pa, bp2);
            fma2(acc[i][3], pa, bp3);
        }
    }
#pragma unroll
    for (int i = 0; i < 4; i++) {
        int o = o0 + oq * 4 + i;
        float bv = cb2[o];
        float v[8];
#pragma unroll
        for (int j = 0; j < 4; j++) {
            float lo, hi;
            unpack2(acc[i][j], lo, hi);
            v[2 * j] = lo + bv; v[2 * j + 1] = hi + bv;
        }
        float* wr = g_w + ((size_t)b * WOUT + o) * P + p0 + px * 8;
        *(float4*)&wr[0] = make_float4(v[0], v[1], v[2], v[3]);
        *(float4*)&wr[4] = make_float4(v[4], v[5], v[6], v[7]);
    }
}

// ---------------- K5: local grouped 3x3 conv (zero pad) ----------------
__global__ __launch_bounds__(256) void localconv_kernel(float* __restrict__ out) {
    const int bg = blockIdx.y;
    const int b = bg >> 5, g = bg & 31;
    const int p = blockIdx.x * 256 + threadIdx.x;
    const int i = p >> 6, j = p & 63;

    const float* wv = g_w + ((size_t)b * WOUT + g * 9) * P + p;
    float w[9];
#pragma unroll
    for (int k = 0; k < 9; k++) w[k] = wv[(size_t)k * P];

    const float* x3 = g_y + ((size_t)b * MID + 64 + g * SHAREC) * P;
    float* ob = out + ((size_t)b * OUTC + g * SHAREC) * P + p;

#pragma unroll
    for (int s = 0; s < SHAREC; s++) {
        const float* xc = x3 + (size_t)s * P;
        float acc = 0.f;
#pragma unroll
        for (int ki = 0; ki < 3; ki++) {
            int ii = i + ki - 1;
            if (ii < 0 || ii > 63) continue;
#pragma unroll
            for (int kj = 0; kj < 3; kj++) {
                int jj = j + kj - 1;
                if (jj < 0 || jj > 63) continue;
                acc += xc[(ii << 6) + jj] * w[ki * 3 + kj];
            }
        }
        ob[(size_t)s * P] = acc;
    }
}

// ---------------- launch ----------------
extern "C" void kernel_launch(void* const* d_in, const int* in_sizes, int n_in,
                              void* d_out, int out_size) {
    const float* x     = (const float*)d_in[0];
    const float* w1    = (const float*)d_in[1];
    const float* b1    = (const float*)d_in[2];
    const float* w2    = (const float*)d_in[3];
    const float* b2    = (const float*)d_in[4];
    const float* w3    = (const float*)d_in[5];
    const float* b3    = (const float*)d_in[6];
    const float* bn1_g = (const float*)d_in[7];
    const float* bn1_b = (const float*)d_in[8];
    const float* bn1_m = (const float*)d_in[9];
    const float* bn1_v = (const float*)d_in[10];
    const float* cw1   = (const float*)d_in[11];
    const float* bn2_g = (const float*)d_in[12];
    const float* bn2_b = (const float*)d_in[13];
    const float* bn2_m = (const float*)d_in[14];
    const float* bn2_v = (const float*)d_in[15];
    const float* cw2   = (const float*)d_in[16];
    const float* cb2   = (const float*)d_in[17];
    float* out = (float*)d_out;

    pack_kernel<<<6, 64>>>(w1, b1, w2, b2, w3, b3,
                           bn1_g, bn1_b, bn1_m, bn1_v,
                           bn2_g, bn2_b, bn2_m, bn2_v);

    {
        dim3 grid(P / 128, MIDP / 128, BB);  // 32 x 3 x 8
        conv1x1_kernel<<<grid, 256>>>(x);
    }
    {
        dim3 grid(P / 256, BB);              // 16 x 8
        wgen1_kernel<<<grid, 256>>>(cw1);
    }
    {
        dim3 grid(P / 256, WOUT / 32, BB);   // 16 x 9 x 8
        wgen2_kernel<<<grid, 256>>>(cw2, cb2);
    }
    {
        dim3 grid(P / 256, BB * GG);         // 16 x 256
        localconv_kernel<<<grid, 256>>>(out);
    }
}

// round 4
// speedup vs baseline: 1.2710x; 1.2710x over previous
#include <cuda_runtime.h>
#include <cuda_bf16.h>
#include <math.h>
#include <stdint.h>

#define BB    8
#define CIN   256
#define OUTC  256
#define SHAREC 8
#define GG    32
#define MID   320
#define MIDP  384
#define WOUT  288
#define P     4096

// ---------------- scratch (static device arrays; no allocation) ----------------
__device__ float g_y[(size_t)BB * MID * P];      // conv1x1 outputs [b][c][p]
__device__ float g_t[(size_t)BB * GG * P];       // weight-gen hidden
__device__ float g_w[(size_t)BB * WOUT * P];     // per-pixel kernels
__device__ float g_bias[MIDP];
__device__ float g_bn1s[MID];
__device__ float g_bn1b[MID];
__device__ float g_bn2s[GG];
__device__ float g_bn2b[GG];
__device__ __nv_bfloat16 g_whi[MIDP * CIN];      // weights hi/lo, [m][k]
__device__ __nv_bfloat16 g_wlo[MIDP * CIN];
__device__ __nv_bfloat16 g_xhi[(size_t)BB * P * CIN];  // x transposed: [b][p][c]
__device__ __nv_bfloat16 g_xlo[(size_t)BB * P * CIN];

__device__ __forceinline__ uint32_t smem_u32(const void* p) {
    uint32_t a;
    asm("{ .reg .u64 t; cvta.to.shared.u64 t, %1; cvt.u32.u64 %0, t; }" : "=r"(a) : "l"(p));
    return a;
}
#define SWZ128(off) ((off) ^ (((off) >> 3) & 0x70))

#define LDSM4(r0, r1, r2, r3, addr) \
    asm volatile("ldmatrix.sync.aligned.m8n8.x4.shared.b16 {%0,%1,%2,%3}, [%4];" \
        : "=r"(r0), "=r"(r1), "=r"(r2), "=r"(r3) : "r"(addr))

#define MMA_BF16(d, a, b) \
    asm volatile("mma.sync.aligned.m16n8k16.row.col.f32.bf16.bf16.f32 " \
        "{%0,%1,%2,%3}, {%4,%5,%6,%7}, {%8,%9}, {%0,%1,%2,%3};" \
        : "+f"((d)[0]), "+f"((d)[1]), "+f"((d)[2]), "+f"((d)[3]) \
        : "r"((a)[0]), "r"((a)[1]), "r"((a)[2]), "r"((a)[3]), "r"((b)[0]), "r"((b)[1]))

// ---------------- K0: pack weights + fold BN params + bf16 split weights ----------------
__global__ void pack_kernel(const float* __restrict__ w1, const float* __restrict__ b1,
                            const float* __restrict__ w2, const float* __restrict__ b2,
                            const float* __restrict__ w3, const float* __restrict__ b3,
                            const float* __restrict__ bn1_g, const float* __restrict__ bn1_b,
                            const float* __restrict__ bn1_m, const float* __restrict__ bn1_v,
                            const float* __restrict__ bn2_g, const float* __restrict__ bn2_b,
                            const float* __restrict__ bn2_m, const float* __restrict__ bn2_v) {
    int c = blockIdx.x * blockDim.x + threadIdx.x;
    if (c >= MIDP) return;
    if (c >= MID) {
        for (int k = 0; k < CIN; k++) {
            g_whi[c * CIN + k] = __float2bfloat16(0.f);
            g_wlo[c * CIN + k] = __float2bfloat16(0.f);
        }
        g_bias[c] = 0.f;
        return;
    }
    const float* src;
    float bv;
    if (c < 32)      { src = w1 + (size_t)c * CIN;        bv = b1[c]; }
    else if (c < 64) { src = w2 + (size_t)(c - 32) * CIN; bv = b2[c - 32]; }
    else             { src = w3 + (size_t)(c - 64) * CIN; bv = b3[c - 64]; }
    for (int k = 0; k < CIN; k++) {
        float v = src[k];
        __nv_bfloat16 hi = __float2bfloat16(v);
        g_whi[c * CIN + k] = hi;
        g_wlo[c * CIN + k] = __float2bfloat16(v - __bfloat162float(hi));
    }
    g_bias[c] = bv;
    float s = bn1_g[c] * rsqrtf(bn1_v[c] + 1e-5f);
    g_bn1s[c] = s;
    g_bn1b[c] = bn1_b[c] - bn1_m[c] * s;
    if (c < GG) {
        float s2 = bn2_g[c] * rsqrtf(bn2_v[c] + 1e-5f);
        g_bn2s[c] = s2;
        g_bn2b[c] = bn2_b[c] - bn2_m[c] * s2;
    }
}

// ---------------- K0b: transpose + split-convert x: [b][c][p] fp32 -> [b][p][c] bf16 hi/lo --------
__global__ __launch_bounds__(256) void xconv_kernel(const float* __restrict__ x) {
    __shared__ float tile[64][33];
    const int b  = blockIdx.z;
    const int c0 = blockIdx.y * 64;
    const int p0 = blockIdx.x * 32;
    const int tid = threadIdx.x;
#pragma unroll
    for (int e = 0; e < 8; e++) {
        int idx = tid + e * 256;
        int c = idx >> 5, j = idx & 31;
        tile[c][j] = x[((size_t)b * CIN + c0 + c) * P + p0 + j];
    }
    __syncthreads();
#pragma unroll
    for (int e = 0; e < 4; e++) {
        int idx = tid + e * 256;
        int p = idx >> 5, cp = idx & 31;
        float f0 = tile[2 * cp][p], f1 = tile[2 * cp + 1][p];
        __nv_bfloat16 h0 = __float2bfloat16(f0);
        __nv_bfloat16 h1 = __float2bfloat16(f1);
        __nv_bfloat16 l0 = __float2bfloat16(f0 - __bfloat162float(h0));
        __nv_bfloat16 l1 = __float2bfloat16(f1 - __bfloat162float(h1));
        size_t off = ((size_t)b * P + p0 + p) * CIN + c0 + 2 * cp;
        *(__nv_bfloat162*)&g_xhi[off] = __nv_bfloat162(h0, h1);
        *(__nv_bfloat162*)&g_xlo[off] = __nv_bfloat162(l0, l1);
    }
}

// ---------------- K1: conv1x1 via mma.sync split-bf16 GEMM ----------------
// CTA: 128 M x 128 N(pixels), K=256 in 4 chunks of 64. 8 warps, warp tile 32x64.
#define KC 64
#define SM_AHI 0
#define SM_ALO 16384
#define SM_BHI 32768
#define SM_BLO 49152
#define SM_TOTAL 65536

__global__ __launch_bounds__(256) void conv_mma_kernel() {
    extern __shared__ char smem[];
    const uint32_t sbase = smem_u32(smem);
    const int tid = threadIdx.x;
    const int wid = tid >> 5;
    const int lid = tid & 31;
    const int b  = blockIdx.z;
    const int m0 = blockIdx.y * 128;
    const int p0 = blockIdx.x * 128;
    const int wm = wid & 3;          // 4 warps along M
    const int wn = wid >> 2;         // 2 warps along N

    float acc[2][8][4];
#pragma unroll
    for (int i = 0; i < 2; i++)
#pragma unroll
        for (int j = 0; j < 8; j++)
#pragma unroll
            for (int q = 0; q < 4; q++) acc[i][j][q] = 0.f;

    // per-lane ldmatrix address components
    const int rowA[2] = { wm * 32 + (lid & 15), wm * 32 + 16 + (lid & 15) };
    const int c16A = (lid >> 4) * 16;
    int rowB[4];
#pragma unroll
    for (int nfp = 0; nfp < 4; nfp++)
        rowB[nfp] = wn * 64 + nfp * 16 + ((lid >> 4) * 8) + (lid & 7);
    const int c16B = ((lid >> 3) & 1) * 16;

    const int rowL = tid >> 3;       // loader: 128 rows, 8 x uint4 per row
    const int ccL  = (tid & 7) * 16; // byte col

    for (int c = 0; c < 4; c++) {
        const int kk = c * KC;
        // ---- load A (128x64 hi+lo) and B (128x64 hi+lo), SW128 swizzled ----
#pragma unroll
        for (int e = 0; e < 4; e++) {
            int row = rowL + e * 32;
            uint32_t dst = (uint32_t)(row * 128 + SWZ128(ccL ^ 0) ) ;
            dst = (uint32_t)(row * 128) + (uint32_t)(ccL ^ ((row & 7) * 16));
            size_t srcA = (size_t)(m0 + row) * CIN + kk + (ccL >> 1);
            *(uint4*)(smem + SM_AHI + dst) = *(const uint4*)&g_whi[srcA];
            *(uint4*)(smem + SM_ALO + dst) = *(const uint4*)&g_wlo[srcA];
            size_t srcB = ((size_t)b * P + p0 + row) * CIN + kk + (ccL >> 1);
            *(uint4*)(smem + SM_BHI + dst) = *(const uint4*)&g_xhi[srcB];
            *(uint4*)(smem + SM_BLO + dst) = *(const uint4*)&g_xlo[srcB];
        }
        __syncthreads();

#pragma unroll
        for (int ks = 0; ks < 4; ks++) {
            const int colA = (ks * 32 + c16A);
            const int colB = (ks * 32 + c16B);
            uint32_t ah[2][4], al[2][4];
#pragma unroll
            for (int mf = 0; mf < 2; mf++) {
                uint32_t off = (uint32_t)(rowA[mf] * 128) +
                               (uint32_t)(colA ^ ((rowA[mf] & 7) * 16));
                LDSM4(ah[mf][0], ah[mf][1], ah[mf][2], ah[mf][3], sbase + SM_AHI + off);
                LDSM4(al[mf][0], al[mf][1], al[mf][2], al[mf][3], sbase + SM_ALO + off);
            }
            uint32_t bh[8][2], bl[8][2];
#pragma unroll
            for (int nfp = 0; nfp < 4; nfp++) {
                uint32_t off = (uint32_t)(rowB[nfp] * 128) +
                               (uint32_t)(colB ^ ((rowB[nfp] & 7) * 16));
                LDSM4(bh[2 * nfp][0], bh[2 * nfp][1], bh[2 * nfp + 1][0], bh[2 * nfp + 1][1],
                      sbase + SM_BHI + off);
                LDSM4(bl[2 * nfp][0], bl[2 * nfp][1], bl[2 * nfp + 1][0], bl[2 * nfp + 1][1],
                      sbase + SM_BLO + off);
            }
#pragma unroll
            for (int mf = 0; mf < 2; mf++)
#pragma unroll
                for (int nf = 0; nf < 8; nf++) {
                    MMA_BF16(acc[mf][nf], ah[mf], bh[nf]);   // hi*hi
                    MMA_BF16(acc[mf][nf], ah[mf], bl[nf]);   // hi*lo
                    MMA_BF16(acc[mf][nf], al[mf], bh[nf]);   // lo*hi
                }
        }
        __syncthreads();
    }

    // ---- epilogue: D layout: d0,d1 @(row=l/4, col=2*(l%4)+{0,1}); d2,d3 @ row+8 ----
    const int r = lid >> 2;
    const int cc = (lid & 3) * 2;
#pragma unroll
    for (int mf = 0; mf < 2; mf++) {
        int m1 = m0 + wm * 32 + mf * 16 + r;
        int m2 = m1 + 8;
        float bv1 = (m1 < MID) ? g_bias[m1] : 0.f;
        float bv2 = (m2 < MID) ? g_bias[m2] : 0.f;
#pragma unroll
        for (int nf = 0; nf < 8; nf++) {
            int p = p0 + wn * 64 + nf * 8 + cc;
            if (m1 < MID) {
                float2 v = make_float2(acc[mf][nf][0] + bv1, acc[mf][nf][1] + bv1);
                *(float2*)&g_y[((size_t)b * MID + m1) * P + p] = v;
            }
            if (m2 < MID) {
                float2 v = make_float2(acc[mf][nf][2] + bv2, acc[mf][nf][3] + bv2);
                *(float2*)&g_y[((size_t)b * MID + m2) * P + p] = v;
            }
        }
    }
}

// ---------------- h(c,p): BN1+ReLU of [x1 ; unfold_reflect(x2)] on the fly ----------------
__device__ __forceinline__ float h_val(const float* __restrict__ yb, int c, int p) {
    float v;
    if (c < 32) {
        v = yb[(size_t)c * P + p];
    } else {
        int cc = c - 32;
        int r = cc / 9, k = cc - r * 9;
        int ki = k / 3 - 1, kj = k - (k / 3) * 3 - 1;
        int i = (p >> 6) + ki;
        int j = (p & 63) + kj;
        i = (i < 0) ? 1 : (i > 63 ? 62 : i);
        j = (j < 0) ? 1 : (j > 63 ? 62 : j);
        v = yb[(size_t)(32 + r) * P + (i << 6) + j];
    }
    v = v * g_bn1s[c] + g_bn1b[c];
    return fmaxf(v, 0.f);
}

// ---------------- K3: t[b,g,p] = relu(bn2( cw1[g,:] . h[b,:,p] )) ----------------
__global__ __launch_bounds__(256) void wgen1_kernel(const float* __restrict__ cw1) {
    const int b  = blockIdx.y;
    const int p0 = blockIdx.x * 128;
    __shared__ float As[16][32];
    __shared__ float Hs[16][128];
    const float* yb = g_y + (size_t)b * MID * P;
    const int tid = threadIdx.x;
    const int px = tid & 31;
    const int gy = tid >> 5;

    float acc[4][4];
#pragma unroll
    for (int i = 0; i < 4; i++)
#pragma unroll
        for (int j = 0; j < 4; j++) acc[i][j] = 0.f;

    for (int kk = 0; kk < MID; kk += 16) {
#pragma unroll
        for (int e = 0; e < 2; e++) {
            int idx = tid + e * 256;
            int k = idx >> 5, g = idx & 31;
            As[k][g] = cw1[g * MID + kk + k];
        }
#pragma unroll
        for (int e = 0; e < 8; e++) {
            int idx = tid + e * 256;
            int k = idx >> 7, n = idx & 127;
            Hs[k][n] = h_val(yb, kk + k, p0 + n);
        }
        __syncthreads();
#pragma unroll
        for (int k = 0; k < 16; k++) {
            float a[4];
#pragma unroll
            for (int i = 0; i < 4; i++) a[i] = As[k][gy + i * 8];
            float4 hv = *(const float4*)&Hs[k][px * 4];
            float hb[4] = {hv.x, hv.y, hv.z, hv.w};
#pragma unroll
            for (int i = 0; i < 4; i++)
#pragma unroll
                for (int j = 0; j < 4; j++) acc[i][j] += a[i] * hb[j];
        }
        __syncthreads();
    }
#pragma unroll
    for (int i = 0; i < 4; i++) {
        int g = gy + i * 8;
        float s = g_bn2s[g], sh = g_bn2b[g];
        float* trow = g_t + ((size_t)b * GG + g) * P + p0 + px * 4;
#pragma unroll
        for (int j = 0; j < 4; j++) trow[j] = fmaxf(acc[i][j] * s + sh, 0.f);
    }
}

// ---------------- K4: w[b,o,p] = cw2[o,:] . t[b,:,p] + cb2[o] ----------------
__global__ __launch_bounds__(256) void wgen2_kernel(const float* __restrict__ cw2,
                                                    const float* __restrict__ cb2) {
    const int b  = blockIdx.y;
    const int p0 = blockIdx.x * 64;
    __shared__ float ts[GG][64];
    __shared__ float w2s[WOUT * GG];
    const int tid = threadIdx.x;

#pragma unroll
    for (int e = 0; e < 8; e++) {
        int idx = tid + e * 256;
        int g = idx >> 6, n = idx & 63;
        ts[g][n] = g_t[((size_t)b * GG + g) * P + p0 + n];
    }
    for (int idx = tid; idx < WOUT * GG; idx += 256) w2s[idx] = cw2[idx];
    __syncthreads();

    const int pp = tid & 63;
    const int q  = tid >> 6;
    float tv[GG];
#pragma unroll
    for (int g = 0; g < GG; g++) tv[g] = ts[g][pp];

    for (int o = q * 72; o < q * 72 + 72; o++) {
        float acc = cb2[o];
#pragma unroll
        for (int g = 0; g < GG; g++) acc += w2s[o * GG + g] * tv[g];
        g_w[((size_t)b * WOUT + o) * P + p0 + pp] = acc;
    }
}

// ---------------- K5: local grouped 3x3 conv (zero pad) ----------------
__global__ __launch_bounds__(256) void localconv_kernel(float* __restrict__ out) {
    const int bg = blockIdx.y;
    const int b = bg >> 5, g = bg & 31;
    const int p = blockIdx.x * 256 + threadIdx.x;
    const int i = p >> 6, j = p & 63;

    const float* wv = g_w + ((size_t)b * WOUT + g * 9) * P + p;
    float w[9];
#pragma unroll
    for (int k = 0; k < 9; k++) w[k] = wv[(size_t)k * P];

    const float* x3 = g_y + ((size_t)b * MID + 64 + g * SHAREC) * P;
    float* ob = out + ((size_t)b * OUTC + g * SHAREC) * P + p;

#pragma unroll
    for (int s = 0; s < SHAREC; s++) {
        const float* xc = x3 + (size_t)s * P;
        float acc = 0.f;
#pragma unroll
        for (int ki = 0; ki < 3; ki++) {
            int ii = i + ki - 1;
            if (ii < 0 || ii > 63) continue;
#pragma unroll
            for (int kj = 0; kj < 3; kj++) {
                int jj = j + kj - 1;
                if (jj < 0 || jj > 63) continue;
                acc += xc[(ii << 6) + jj] * w[ki * 3 + kj];
            }
        }
        ob[(size_t)s * P] = acc;
    }
}

// ---------------- launch ----------------
extern "C" void kernel_launch(void* const* d_in, const int* in_sizes, int n_in,
                              void* d_out, int out_size) {
    const float* x     = (const float*)d_in[0];
    const float* w1    = (const float*)d_in[1];
    const float* b1    = (const float*)d_in[2];
    const float* w2    = (const float*)d_in[3];
    const float* b2    = (const float*)d_in[4];
    const float* w3    = (const float*)d_in[5];
    const float* b3    = (const float*)d_in[6];
    const float* bn1_g = (const float*)d_in[7];
    const float* bn1_b = (const float*)d_in[8];
    const float* bn1_m = (const float*)d_in[9];
    const float* bn1_v = (const float*)d_in[10];
    const float* cw1   = (const float*)d_in[11];
    const float* bn2_g = (const float*)d_in[12];
    const float* bn2_b = (const float*)d_in[13];
    const float* bn2_m = (const float*)d_in[14];
    const float* bn2_v = (const float*)d_in[15];
    const float* cw2   = (const float*)d_in[16];
    const float* cb2   = (const float*)d_in[17];
    float* out = (float*)d_out;

    static int smem_set = 0;
    if (!smem_set) {
        cudaFuncSetAttribute(conv_mma_kernel,
                             cudaFuncAttributeMaxDynamicSharedMemorySize, SM_TOTAL);
        smem_set = 1;
    }

    pack_kernel<<<6, 64>>>(w1, b1, w2, b2, w3, b3,
                           bn1_g, bn1_b, bn1_m, bn1_v,
                           bn2_g, bn2_b, bn2_m, bn2_v);
    {
        dim3 grid(P / 32, CIN / 64, BB);      // 128 x 4 x 8
        xconv_kernel<<<grid, 256>>>(x);
    }
    {
        dim3 grid(P / 128, MIDP / 128, BB);   // 32 x 3 x 8
        conv_mma_kernel<<<grid, 256, SM_TOTAL>>>();
    }
    {
        dim3 grid(P / 128, BB);
        wgen1_kernel<<<grid, 256>>>(cw1);
    }
    {
        dim3 grid(P / 64, BB);
        wgen2_kernel<<<grid, 256>>>(cw2, cb2);
    }
    {
        dim3 grid(P / 256, BB * GG);
        localconv_kernel<<<grid, 256>>>(out);
    }
}